// round 17
// baseline (speedup 1.0000x reference)
#include <cuda_runtime.h>

// Problem shape (fixed by the dataset)
#define BB 4
#define NN 8192
#define MM 2048
#define FF 256
#define KK 16
#define CH (3 + FF)   // 259 output channels
#define NG 256        // groups of 32 sorted points per batch

// Scratch (static __device__ — no allocations allowed)
__device__ __align__(16) float4 g_pts4 [BB * NN];  // packed xyz + |p|^2 (orig order)
__device__ __align__(16) float4 g_pts4s[BB * NN];  // sorted by Morton code
__device__ int    g_sidx[BB * NN];                 // sorted pos -> original index
__device__ __align__(16) float4 g_grp [BB * NG];   // group centroid xyz + radius
__device__ int    g_idx [BB * MM * KK];            // neighbor indices (original)
__device__ float  g_w   [BB * MM * KK];            // softmax weights
__device__ __align__(16) float g_T[(size_t)BB * NN * FF];  // (B,N,F), 33.5MB

// ---------------------------------------------------------------------------
// K0: pack point cloud (B,3,N) -> float4 (x,y,z,|p|^2)
// ---------------------------------------------------------------------------
__global__ void k_pack(const float* __restrict__ pc) {
    int i = blockIdx.x * blockDim.x + threadIdx.x;
    if (i >= BB * NN) return;
    int b = i / NN, n = i - b * NN;
    const float* base = pc + (size_t)b * 3 * NN;
    float x = base[n], y = base[NN + n], z = base[2 * NN + n];
    g_pts4[i] = make_float4(x, y, z, fmaf(x, x, fmaf(y, y, z * z)));
}

// ---------------------------------------------------------------------------
// Monotonic float<->uint mapping (for atomicMin/Max-based bbox reduction)
// ---------------------------------------------------------------------------
__device__ __forceinline__ unsigned mono(float f) {
    unsigned u = __float_as_uint(f);
    return (u & 0x80000000u) ? ~u : (u | 0x80000000u);
}
__device__ __forceinline__ float unmono(unsigned u) {
    return __uint_as_float((u & 0x80000000u) ? (u ^ 0x80000000u) : ~u);
}
__device__ __forceinline__ unsigned expand3(unsigned v) {  // 10 bits -> every 3rd
    v = (v | (v << 16)) & 0x030000FFu;
    v = (v | (v << 8))  & 0x0300F00Fu;
    v = (v | (v << 4))  & 0x030C30C3u;
    v = (v | (v << 2))  & 0x09249249u;
    return v;
}

// ---------------------------------------------------------------------------
// KS: per-batch Morton sort. One 1024-thread block per batch; 8192 u64 keys
// (morton<<13 | idx, unique) bitonic-sorted in 64KB dynamic smem.
// ---------------------------------------------------------------------------
extern __shared__ unsigned long long s_keys[];
__global__ void k_sort() {
    __shared__ unsigned s_bmin[3], s_bmax[3];
    int b = blockIdx.x, t = threadIdx.x, lane = t & 31;
    const float4* P = g_pts4 + (size_t)b * NN;

    if (t < 3) { s_bmin[t] = 0xFFFFFFFFu; s_bmax[t] = 0u; }
    __syncthreads();

    // bbox reduction
    float mnx = 3.4e38f, mny = 3.4e38f, mnz = 3.4e38f;
    float mxx = -3.4e38f, mxy = -3.4e38f, mxz = -3.4e38f;
    for (int i = t; i < NN; i += 1024) {
        float4 p = P[i];
        mnx = fminf(mnx, p.x); mxx = fmaxf(mxx, p.x);
        mny = fminf(mny, p.y); mxy = fmaxf(mxy, p.y);
        mnz = fminf(mnz, p.z); mxz = fmaxf(mxz, p.z);
    }
    #pragma unroll
    for (int off = 16; off >= 1; off >>= 1) {
        mnx = fminf(mnx, __shfl_xor_sync(0xFFFFFFFFu, mnx, off));
        mny = fminf(mny, __shfl_xor_sync(0xFFFFFFFFu, mny, off));
        mnz = fminf(mnz, __shfl_xor_sync(0xFFFFFFFFu, mnz, off));
        mxx = fmaxf(mxx, __shfl_xor_sync(0xFFFFFFFFu, mxx, off));
        mxy = fmaxf(mxy, __shfl_xor_sync(0xFFFFFFFFu, mxy, off));
        mxz = fmaxf(mxz, __shfl_xor_sync(0xFFFFFFFFu, mxz, off));
    }
    if (lane == 0) {
        atomicMin(&s_bmin[0], mono(mnx)); atomicMax(&s_bmax[0], mono(mxx));
        atomicMin(&s_bmin[1], mono(mny)); atomicMax(&s_bmax[1], mono(mxy));
        atomicMin(&s_bmin[2], mono(mnz)); atomicMax(&s_bmax[2], mono(mxz));
    }
    __syncthreads();
    float bx = unmono(s_bmin[0]), by = unmono(s_bmin[1]), bz = unmono(s_bmin[2]);
    float sx = 1023.0f / fmaxf(unmono(s_bmax[0]) - bx, 1e-20f);
    float sy = 1023.0f / fmaxf(unmono(s_bmax[1]) - by, 1e-20f);
    float sz = 1023.0f / fmaxf(unmono(s_bmax[2]) - bz, 1e-20f);

    // Morton keys
    for (int i = t; i < NN; i += 1024) {
        float4 p = P[i];
        unsigned xi = (unsigned)fminf(fmaxf((p.x - bx) * sx, 0.f), 1023.f);
        unsigned yi = (unsigned)fminf(fmaxf((p.y - by) * sy, 0.f), 1023.f);
        unsigned zi = (unsigned)fminf(fmaxf((p.z - bz) * sz, 0.f), 1023.f);
        unsigned m = (expand3(zi) << 2) | (expand3(yi) << 1) | expand3(xi);
        s_keys[i] = ((unsigned long long)m << 13) | (unsigned)i;
    }

    // bitonic sort (unique keys -> deterministic order)
    for (int k2 = 2; k2 <= NN; k2 <<= 1) {
        for (int j = k2 >> 1; j > 0; j >>= 1) {
            __syncthreads();
            #pragma unroll 1
            for (int i = t; i < NN; i += 1024) {
                int p2 = i ^ j;
                if (p2 > i) {
                    unsigned long long a = s_keys[i], c = s_keys[p2];
                    bool up = ((i & k2) == 0);
                    if ((a > c) == up) { s_keys[i] = c; s_keys[p2] = a; }
                }
            }
        }
    }
    __syncthreads();

    // scatter
    for (int i = t; i < NN; i += 1024) {
        int n = (int)(s_keys[i] & 8191u);
        g_pts4s[(size_t)b * NN + i] = P[n];
        g_sidx [(size_t)b * NN + i] = n;
    }
}

// ---------------------------------------------------------------------------
// KG: group centroids + conservative radii. One warp per 32-point group.
// ---------------------------------------------------------------------------
__global__ void k_groups() {
    int w = (blockIdx.x * blockDim.x + threadIdx.x) >> 5;  // group id in [0, BB*NG)
    int lane = threadIdx.x & 31;
    int b = w >> 8, g = w & 255;
    float4 p = g_pts4s[(size_t)b * NN + g * 32 + lane];
    float cx = p.x, cy = p.y, cz = p.z;
    #pragma unroll
    for (int off = 16; off >= 1; off >>= 1) {
        cx += __shfl_xor_sync(0xFFFFFFFFu, cx, off);
        cy += __shfl_xor_sync(0xFFFFFFFFu, cy, off);
        cz += __shfl_xor_sync(0xFFFFFFFFu, cz, off);
    }
    cx *= (1.0f / 32.0f); cy *= (1.0f / 32.0f); cz *= (1.0f / 32.0f);
    float dx = p.x - cx, dy = p.y - cy, dz = p.z - cz;
    float d2 = fmaf(dx, dx, fmaf(dy, dy, dz * dz));
    #pragma unroll
    for (int off = 16; off >= 1; off >>= 1)
        d2 = fmaxf(d2, __shfl_xor_sync(0xFFFFFFFFu, d2, off));
    if (lane == 0)
        g_grp[w] = make_float4(cx, cy, cz, sqrtf(d2) * 1.00002f + 1e-6f);
}

// ---------------------------------------------------------------------------
// K1: pruned warp-per-query KNN (8192 warps — proven occupancy regime).
// Bootstrap: nearest-centroid group, bitonic top-16 (exact). Then every
// group faces a conservative exclusion test (|q-c|-r)^2 > tau_true,
// re-evaluated as tau tightens; surviving groups are scanned EXACTLY like
// the flat version. Exclusion is provably safe: lb > tau_now >= tau_final.
// Distances d' = |p|^2 - 2 q.p (offset by -|q|^2: same order, softmax
// differences cancel the offset exactly).
// ---------------------------------------------------------------------------
__global__ void k_knn(const float* __restrict__ qc,
                      const float* __restrict__ temp,
                      float* __restrict__ out) {
    const unsigned FULL = 0xFFFFFFFFu;
    int gw   = (blockIdx.x * blockDim.x + threadIdx.x) >> 5;  // query id
    int lane = threadIdx.x & 31;
    int b = gw / MM, m = gw - b * MM;

    const float* qb = qc + (size_t)b * 3 * MM;
    float qx = qb[m], qy = qb[MM + m], qz = qb[2 * MM + m];
    float q2 = fmaf(qx, qx, fmaf(qy, qy, qz * qz));
    float n2x = -2.0f * qx, n2y = -2.0f * qy, n2z = -2.0f * qz;

    const float4* pts = g_pts4s + (size_t)b * NN;
    const float4* grp = g_grp   + (size_t)b * NG;

    float ld; int li; float tau;

#define PROCESS(dv, boff)                                                   \
    {                                                                        \
        unsigned ball = __ballot_sync(FULL, (dv) < tau);                     \
        if (ball) {                                                          \
            do {                                                             \
                int src = __ffs(ball) - 1;                                   \
                ball &= ball - 1;                                            \
                float dc = __shfl_sync(FULL, (dv), src);                     \
                int ic = (boff) + src;                                       \
                unsigned less = __ballot_sync(FULL, ld < dc);                \
                int pos = __popc(less);        /* 16 -> provable no-op */    \
                float pld = __shfl_up_sync(FULL, ld, 1);                     \
                int   pli = __shfl_up_sync(FULL, li, 1);                     \
                if (lane < KK) {                                             \
                    if (lane > pos)       { ld = pld; li = pli; }            \
                    else if (lane == pos) { ld = dc;  li = ic;  }            \
                }                                                            \
            } while (ball);                                                  \
            tau = __shfl_sync(FULL, ld, KK - 1);                             \
        }                                                                    \
    }

    // ---- nearest-centroid group (warp argmin, deterministic tie-break) ----
    float bestd = 3.4e38f; int bg = 0;
    #pragma unroll
    for (int it = 0; it < 8; it++) {
        float4 c = grp[it * 32 + lane];
        float ex = c.x - qx, ey = c.y - qy, ez = c.z - qz;
        float dd = fmaf(ex, ex, fmaf(ey, ey, ez * ez));
        if (dd < bestd) { bestd = dd; bg = it * 32 + lane; }
    }
    #pragma unroll
    for (int off = 16; off >= 1; off >>= 1) {
        float od = __shfl_xor_sync(FULL, bestd, off);
        int   og = __shfl_xor_sync(FULL, bg, off);
        if (od < bestd || (od == bestd && og < bg)) { bestd = od; bg = og; }
    }

    // ---- bootstrap: exact bitonic top-16 of group bg ----
    {
        int j0 = bg * 32;
        float4 p = pts[j0 + lane];
        float d = fmaf(p.x, n2x, fmaf(p.y, n2y, fmaf(p.z, n2z, p.w)));
        float sd = d; int si = j0 + lane;
        #pragma unroll
        for (int k = 2; k <= 32; k <<= 1) {
            #pragma unroll
            for (int j = k >> 1; j > 0; j >>= 1) {
                float od = __shfl_xor_sync(FULL, sd, j);
                int   oi = __shfl_xor_sync(FULL, si, j);
                bool keep_min = (((lane & k) == 0) == ((lane & j) == 0));
                bool take_other = keep_min ? (od < sd) : (od > sd);
                if (take_other) { sd = od; si = oi; }
            }
        }
        ld  = (lane < KK) ? sd : __int_as_float(0x7f800000);
        li  = si;
        tau = __shfl_sync(FULL, ld, KK - 1);
    }

    // ---- pruned scan: 8 batches of 32 groups, lane-owned bound tests ----
    for (int batch = 0; batch < 8; batch++) {
        int gid = batch * 32 + lane;
        float4 c = grp[gid];
        float ex = c.x - qx, ey = c.y - qy, ez = c.z - qz;
        float dcq = fmaf(ex, ex, fmaf(ey, ey, ez * ez));
        bool done = (gid == bg);                 // never rescan bootstrap group
        while (true) {
            float s = sqrtf(fmaxf(tau + q2, 0.0f));   // tau_true = tau + |q|^2
            float rhs = s + c.w;
            rhs = rhs * rhs * 1.00002f;               // conservative inflation
            unsigned ball = __ballot_sync(FULL, (!done) && (dcq <= rhs));
            if (!ball) break;
            int sel = __ffs(ball) - 1;
            if (lane == sel) done = true;
            int jb = (batch * 32 + sel) * 32;
            float4 pp = pts[jb + lane];
            float dd = fmaf(pp.x, n2x, fmaf(pp.y, n2y, fmaf(pp.z, n2z, pp.w)));
            PROCESS(dd, jb);
        }
    }
#undef PROCESS

    // ---- softmax(-(d - dmin)/sigma) over the 16 neighbors ----
    float tv    = *temp;
    float sigma = fmaxf(tv * tv, 1e-4f);
    float dmin  = __shfl_sync(FULL, ld, 0);
    float e = (lane < KK) ? __expf((dmin - ld) / sigma) : 0.0f;
    float s = e;
    #pragma unroll
    for (int off = 16; off >= 1; off >>= 1) s += __shfl_xor_sync(FULL, s, off);
    float w = e / s;

    if (lane < KK) {
        g_idx[gw * KK + lane] = g_sidx[(size_t)b * NN + li];  // map to original
        g_w  [gw * KK + lane] = w;
    }

    // projected points = sum_j w_j * p_j (sorted array has same coords)
    float4 gp = make_float4(0.f, 0.f, 0.f, 0.f);
    if (lane < KK) gp = pts[li];
    float sx = w * gp.x, sy = w * gp.y, sz = w * gp.z;
    #pragma unroll
    for (int off = 16; off >= 1; off >>= 1) {
        sx += __shfl_xor_sync(FULL, sx, off);
        sy += __shfl_xor_sync(FULL, sy, off);
        sz += __shfl_xor_sync(FULL, sz, off);
    }
    if (lane == 0) {
        float* ob = out + (size_t)b * CH * MM;
        ob[m]          = sx;
        ob[MM + m]     = sy;
        ob[2 * MM + m] = sz;
    }
}

// ---------------------------------------------------------------------------
// K2: transpose features (B,F,N) -> (B,N,F). float4 both directions through
// a padded conflict-free 32x32 tile.
// ---------------------------------------------------------------------------
__global__ void k_transpose(const float* __restrict__ feat) {
    __shared__ float t[32][33];
    int b  = blockIdx.z;
    int n0 = blockIdx.x * 32, f0 = blockIdx.y * 32;
    int tid = threadIdx.x;                 // 256 threads
    const float* fb = feat + (size_t)b * FF * NN;

    int f = tid >> 3, nc = tid & 7;
    float4 v = *(const float4*)(fb + (size_t)(f0 + f) * NN + n0 + 4 * nc);
    t[4 * nc + 0][f] = v.x;
    t[4 * nc + 1][f] = v.y;
    t[4 * nc + 2][f] = v.z;
    t[4 * nc + 3][f] = v.w;
    __syncthreads();

    int n = tid >> 3, fc = tid & 7;
    float4 w = make_float4(t[n][4 * fc], t[n][4 * fc + 1],
                           t[n][4 * fc + 2], t[n][4 * fc + 3]);
    *(float4*)(g_T + (size_t)b * NN * FF + (size_t)(n0 + n) * FF + f0 + 4 * fc) = w;
}

// ---------------------------------------------------------------------------
// K3 (fused gather + output transpose), unchanged from the 80us version.
// ---------------------------------------------------------------------------
__global__ void k_gather_out(float* __restrict__ out) {
    __shared__ int   sidx[32][KK];
    __shared__ float sw  [32][KK];
    __shared__ float tile[32][33];

    int tid = threadIdx.x;           // 256 threads
    int f0 = blockIdx.x * 32;
    int m0 = blockIdx.y * 32;
    int b  = blockIdx.z;

    {
        int base = (b * MM + m0) * KK;
        #pragma unroll
        for (int t2 = tid; t2 < 32 * KK; t2 += 256) {
            ((int*)sidx)[t2] = g_idx[base + t2];
            ((float*)sw)[t2] = g_w  [base + t2];
        }
    }
    __syncthreads();

    int qi = tid >> 3;
    int xq = tid & 7;
    const float4* Tb4 = (const float4*)(g_T + (size_t)b * NN * FF) + (f0 >> 2) + xq;
    float4 acc = make_float4(0.f, 0.f, 0.f, 0.f);
    #pragma unroll
    for (int j = 0; j < KK; j++) {
        float  wj = sw[qi][j];
        float4 v  = Tb4[(size_t)sidx[qi][j] * (FF / 4)];
        acc.x = fmaf(wj, v.x, acc.x);
        acc.y = fmaf(wj, v.y, acc.y);
        acc.z = fmaf(wj, v.z, acc.z);
        acc.w = fmaf(wj, v.w, acc.w);
    }
    tile[4 * xq + 0][qi] = acc.x;
    tile[4 * xq + 1][qi] = acc.y;
    tile[4 * xq + 2][qi] = acc.z;
    tile[4 * xq + 3][qi] = acc.w;
    __syncthreads();

    int x  = tid & 31;
    int y0 = tid >> 5;
    float* dst = out + (size_t)b * CH * MM;
    #pragma unroll
    for (int r = 0; r < 4; r++) {
        int f = y0 + r * 8;
        dst[(size_t)(3 + f0 + f) * MM + m0 + x] = tile[f][x];
    }
}

// ---------------------------------------------------------------------------
// Side stream: transpose overlaps ONLY pack/sort/groups (which occupy <=5
// SMs). Main stream WAITS for the transpose before knn -> no contention with
// the occupancy-sensitive knn (round-7 lesson). Stream/events created once;
// every call performs the identical deterministic launch sequence.
// ---------------------------------------------------------------------------
static cudaStream_t g_s2;
static cudaEvent_t  g_e_fork, g_e_join;
static bool         g_init_done = false;

extern "C" void kernel_launch(void* const* d_in, const int* in_sizes, int n_in,
                              void* d_out, int out_size) {
    (void)in_sizes; (void)n_in; (void)out_size;
    const float* pc   = (const float*)d_in[0];  // (B,3,N)
    const float* qc   = (const float*)d_in[1];  // (B,3,M)
    const float* feat = (const float*)d_in[2];  // (B,F,N)
    const float* temp = (const float*)d_in[3];  // scalar
    float* out = (float*)d_out;                 // (B,259,M)

    if (!g_init_done) {
        cudaStreamCreateWithFlags(&g_s2, cudaStreamNonBlocking);
        cudaEventCreateWithFlags(&g_e_fork, cudaEventDisableTiming);
        cudaEventCreateWithFlags(&g_e_join, cudaEventDisableTiming);
        g_init_done = true;
    }
    cudaFuncSetAttribute(k_sort, cudaFuncAttributeMaxDynamicSharedMemorySize,
                         NN * (int)sizeof(unsigned long long));

    // fork: transpose on side stream (independent of everything else)
    cudaEventRecord(g_e_fork, 0);
    cudaStreamWaitEvent(g_s2, g_e_fork, 0);
    k_transpose<<<dim3(NN / 32, FF / 32, BB), 256, 0, g_s2>>>(feat);
    cudaEventRecord(g_e_join, g_s2);

    // main: pack -> sort -> groups (few-SM phase, overlapped with transpose)
    k_pack<<<(BB * NN + 255) / 256, 256>>>(pc);
    k_sort<<<BB, 1024, NN * sizeof(unsigned long long)>>>();
    k_groups<<<(BB * NG) / 8, 256>>>();

    // wait for transpose BEFORE knn so knn runs uncontended at full occupancy
    cudaStreamWaitEvent(0, g_e_join, 0);
    k_knn<<<(BB * MM) / 8, 256>>>(qc, temp, out);
    k_gather_out<<<dim3(FF / 32, MM / 32, BB), 256>>>(out);
}